// round 8
// baseline (speedup 1.0000x reference)
#include <cuda_runtime.h>
#include <float.h>

#define BB 4096
#define NN 2048
#define NPAIR 3
#define THREADS 256              // 8 warps per CTA
#define NWARPS (BB * NPAIR)      // 12288 warps, one per (pair,row)
#define NCTAS (NWARPS / 8)       // 1536 CTAs
#define RED_THREADS 1024

// Per-(pair,row) weighted contributions. Deterministic fixed-order final sum.
__device__ float g_partials[NPAIR * BB];

__global__ __launch_bounds__(THREADS)
void wnrmse_row_kernel(const float* __restrict__ o1, const float* __restrict__ t1,
                       const float* __restrict__ o2, const float* __restrict__ t2,
                       const float* __restrict__ o3, const float* __restrict__ t3) {
    const int l  = threadIdx.x & 31;
    const int gw = blockIdx.x * 8 + (threadIdx.x >> 5);  // global warp id = p*BB + b
    const int p  = gw >> 12;            // pair (BB = 4096 = 2^12)
    const int b  = gw & (BB - 1);       // batch row

    const float* o = (p == 0) ? o1 : ((p == 1) ? o2 : o3);
    const float* t = (p == 0) ? t1 : ((p == 1) ? t2 : t3);

    const float4* __restrict__ o4 = reinterpret_cast<const float4*>(o + (size_t)b * NN);
    const float4* __restrict__ t4 = reinterpret_cast<const float4*>(t + (size_t)b * NN);

    float ssq = 0.0f, tmax = -FLT_MAX, tmin = FLT_MAX;

    // Row = 512 float4 per tensor; 32 lanes -> 16 float4/lane/tensor.
    // 4 chunks x (4 o-loads + 4 t-loads). No barriers anywhere: ptxas is free
    // to hoist the next chunk's loads over this chunk's FMAs.
    #pragma unroll
    for (int c = 0; c < 4; c++) {
        const int base = l + c * 128;   // c*4*32
        float4 a0 = o4[base];
        float4 a1 = o4[base + 32];
        float4 a2 = o4[base + 64];
        float4 a3 = o4[base + 96];
        float4 b0 = t4[base];
        float4 b1 = t4[base + 32];
        float4 b2 = t4[base + 64];
        float4 b3 = t4[base + 96];

        float d;
        d = a0.x - b0.x; ssq = fmaf(d, d, ssq); tmax = fmaxf(tmax, b0.x); tmin = fminf(tmin, b0.x);
        d = a0.y - b0.y; ssq = fmaf(d, d, ssq); tmax = fmaxf(tmax, b0.y); tmin = fminf(tmin, b0.y);
        d = a0.z - b0.z; ssq = fmaf(d, d, ssq); tmax = fmaxf(tmax, b0.z); tmin = fminf(tmin, b0.z);
        d = a0.w - b0.w; ssq = fmaf(d, d, ssq); tmax = fmaxf(tmax, b0.w); tmin = fminf(tmin, b0.w);
        d = a1.x - b1.x; ssq = fmaf(d, d, ssq); tmax = fmaxf(tmax, b1.x); tmin = fminf(tmin, b1.x);
        d = a1.y - b1.y; ssq = fmaf(d, d, ssq); tmax = fmaxf(tmax, b1.y); tmin = fminf(tmin, b1.y);
        d = a1.z - b1.z; ssq = fmaf(d, d, ssq); tmax = fmaxf(tmax, b1.z); tmin = fminf(tmin, b1.z);
        d = a1.w - b1.w; ssq = fmaf(d, d, ssq); tmax = fmaxf(tmax, b1.w); tmin = fminf(tmin, b1.w);
        d = a2.x - b2.x; ssq = fmaf(d, d, ssq); tmax = fmaxf(tmax, b2.x); tmin = fminf(tmin, b2.x);
        d = a2.y - b2.y; ssq = fmaf(d, d, ssq); tmax = fmaxf(tmax, b2.y); tmin = fminf(tmin, b2.y);
        d = a2.z - b2.z; ssq = fmaf(d, d, ssq); tmax = fmaxf(tmax, b2.z); tmin = fminf(tmin, b2.z);
        d = a2.w - b2.w; ssq = fmaf(d, d, ssq); tmax = fmaxf(tmax, b2.w); tmin = fminf(tmin, b2.w);
        d = a3.x - b3.x; ssq = fmaf(d, d, ssq); tmax = fmaxf(tmax, b3.x); tmin = fminf(tmin, b3.x);
        d = a3.y - b3.y; ssq = fmaf(d, d, ssq); tmax = fmaxf(tmax, b3.y); tmin = fminf(tmin, b3.y);
        d = a3.z - b3.z; ssq = fmaf(d, d, ssq); tmax = fmaxf(tmax, b3.z); tmin = fminf(tmin, b3.z);
        d = a3.w - b3.w; ssq = fmaf(d, d, ssq); tmax = fmaxf(tmax, b3.w); tmin = fminf(tmin, b3.w);
    }

    // Warp-local reduce; no smem, no bar.sync.
    #pragma unroll
    for (int s = 16; s > 0; s >>= 1) {
        ssq  += __shfl_xor_sync(0xFFFFFFFFu, ssq,  s);
        tmax  = fmaxf(tmax, __shfl_xor_sync(0xFFFFFFFFu, tmax, s));
        tmin  = fminf(tmin, __shfl_xor_sync(0xFFFFFFFFu, tmin, s));
    }

    if (l == 0) {
        const float wgt = (p == 0) ? 0.5f : 0.25f;
        g_partials[gw] = wgt * sqrtf(ssq * (1.0f / NN)) / (tmax - tmin);
    }
}

// Tail (PDL): overlaps its launch front-end with the primary's drain.
__global__ __launch_bounds__(RED_THREADS)
void wnrmse_reduce_kernel(float* __restrict__ out) {
    cudaGridDependencySynchronize();

    const int tid = threadIdx.x;
    const float4* __restrict__ p4 = reinterpret_cast<const float4*>(g_partials);

    float4 v0 = p4[tid];
    float4 v1 = p4[tid + RED_THREADS];
    float4 v2 = p4[tid + 2 * RED_THREADS];

    float s = ((v0.x + v0.y) + (v0.z + v0.w))
            + ((v1.x + v1.y) + (v1.z + v1.w))
            + ((v2.x + v2.y) + (v2.z + v2.w));

    #pragma unroll
    for (int sh = 16; sh > 0; sh >>= 1)
        s += __shfl_xor_sync(0xFFFFFFFFu, s, sh);

    __shared__ float s_part[32];
    const int w = tid >> 5, l = tid & 31;
    if (l == 0) s_part[w] = s;
    __syncthreads();
    if (w == 0) {
        float a = s_part[l];   // exactly 32 warps
        #pragma unroll
        for (int sh = 16; sh > 0; sh >>= 1)
            a += __shfl_xor_sync(0xFFFFFFFFu, a, sh);
        if (l == 0) out[0] = a * (1.0f / BB);
    }
}

extern "C" void kernel_launch(void* const* d_in, const int* in_sizes, int n_in,
                              void* d_out, int out_size) {
    const float* o1 = (const float*)d_in[0];
    const float* t1 = (const float*)d_in[1];
    const float* o2 = (const float*)d_in[2];
    const float* t2 = (const float*)d_in[3];
    const float* o3 = (const float*)d_in[4];
    const float* t3 = (const float*)d_in[5];
    float* out = (float*)d_out;

    wnrmse_row_kernel<<<NCTAS, THREADS>>>(o1, t1, o2, t2, o3, t3);

    cudaLaunchConfig_t cfg = {};
    cfg.gridDim = dim3(1, 1, 1);
    cfg.blockDim = dim3(RED_THREADS, 1, 1);
    cfg.dynamicSmemBytes = 0;
    cfg.stream = 0;
    cudaLaunchAttribute attrs[1];
    attrs[0].id = cudaLaunchAttributeProgrammaticStreamSerialization;
    attrs[0].val.programmaticStreamSerializationAllowed = 1;
    cfg.attrs = attrs;
    cfg.numAttrs = 1;
    cudaLaunchKernelEx(&cfg, wnrmse_reduce_kernel, out);
}